// round 15
// baseline (speedup 1.0000x reference)
#include <cuda_runtime.h>
#include <cuda_fp16.h>
#include <cstdint>

#define NUM_E 100000
#define DZ    384
#define MEMD  256
#define NODED 128
#define E_PAD 100096           // 1564 * 64
#define BM 64
#define BN 64
#define KB 64                  // K halves per chunk
#define NCH (DZ/KB)            // 6 chunks

#define ZSTR 72
#define WSTR 72
#define ZHALVES (3*64*ZSTR)    // 13824
#define WHALVES (2*64*WSTR)    // 9216
#define STAGE_H (ZHALVES + WHALVES)          // 23040 halves
#define SMEM_BYTES (2 * STAGE_H * 2 + 1536)  // 93696 B (stages + ids/rts)

// weights (fp16) + per-edge resolved ids / rel-times (padded to E_PAD)
__device__ __align__(16) __half g_wl[DZ * DZ];
__device__ __align__(16) __half g_wd[DZ * DZ];
__device__ int   g_id3[3 * E_PAD];
__device__ float g_rt3[3 * E_PAD];

__device__ __forceinline__ void mma_f16(float* c,
    uint32_t a0, uint32_t a1, uint32_t a2, uint32_t a3,
    uint32_t b0, uint32_t b1)
{
    asm volatile(
        "mma.sync.aligned.m16n8k16.row.col.f32.f16.f16.f32 "
        "{%0,%1,%2,%3},{%4,%5,%6,%7},{%8,%9},{%0,%1,%2,%3};"
        : "+f"(c[0]), "+f"(c[1]), "+f"(c[2]), "+f"(c[3])
        : "r"(a0), "r"(a1), "r"(a2), "r"(a3), "r"(b0), "r"(b1));
}
__device__ __forceinline__ void ldsm4(uint32_t* r, uint32_t addr) {
    asm volatile("ldmatrix.sync.aligned.m8n8.x4.shared.b16 {%0,%1,%2,%3}, [%4];"
                 : "=r"(r[0]), "=r"(r[1]), "=r"(r[2]), "=r"(r[3]) : "r"(addr));
}

// ---------------------------------------------------------------------------
// Resolve (+ weight conversion): y in {0,1,2} id chains (padded rows -> id 0,
// rt 0, results discarded later); y == 3 converts weights. Seeds outputs.
// ---------------------------------------------------------------------------
__global__ void resolve(
    const float* __restrict__ lu, const float* __restrict__ bt,
    const float* __restrict__ bfin,
    const float* __restrict__ wlf, const float* __restrict__ wdf,
    const int* __restrict__ nid, const int* __restrict__ idmap,
    const int* __restrict__ src, const int* __restrict__ pdst,
    const int* __restrict__ ndst,
    float* __restrict__ out)
{
    int e = blockIdx.x * blockDim.x + threadIdx.x;
    int w = blockIdx.y;
    if (w == 3) {
        for (int i = e; i < DZ * DZ; i += gridDim.x * blockDim.x) {
            g_wl[i] = __float2half_rn(wlf[i]);
            g_wd[i] = __float2half_rn(wdf[i]);
        }
        return;
    }
    if (e >= E_PAD) return;
    int gid = 0; float rtv = 0.f;
    if (e < NUM_E) {
        const int* idx = (w == 0) ? src : (w == 1) ? pdst : ndst;
        gid = nid[idmap[idx[e]]];
        rtv = fabsf(lu[gid] - bt[e]);
    }
    g_id3[w * E_PAD + e] = gid;
    g_rt3[w * E_PAD + e] = rtv;
    if (w == 0 && e < NUM_E) {
        float bfv = bfin[0];
        out[e]         = bfv;
        out[NUM_E + e] = bfv;
    }
}

// ---------------------------------------------------------------------------
// Fused gather + triple fp16 GEMM + readout. Each CTA gathers its own 64
// edges' z-rows chunk-by-chunk (LDG fp32 -> scale -> half2 STS into the next
// stage), interleaved between kk MMA steps. No global z-scratch at all.
// 256 threads = 8 warps (4M x 2N), block tile 64x64, KB=64, 2 CTAs/SM.
// nblk 0/1 CTAs also emit the m[i_src]/m[i_pos] passthrough outputs.
// ---------------------------------------------------------------------------
__global__ __launch_bounds__(256, 2) void gemm_fused(
    const float* __restrict__ mem, const float* __restrict__ x,
    const float* __restrict__ wps, const float* __restrict__ bps,
    const float* __restrict__ wpd, const float* __restrict__ bpd,
    const float* __restrict__ bl,  const float* __restrict__ bd,
    const float* __restrict__ wf,
    float* __restrict__ out)
{
    extern __shared__ __half sm[];
    uint32_t sbase = (uint32_t)__cvta_generic_to_shared(sm);
    int*   sm_id = (int*)(sm + 2 * STAGE_H);
    float* sm_rt = (float*)(sm_id + 192);

    int tid  = threadIdx.x;
    int wid  = tid >> 5, lane = tid & 31;
    int grp  = lane >> 2, qid = lane & 3;
    int wm   = wid & 3,  wn  = wid >> 2;
    int m0   = blockIdx.y * BM;
    int n0   = blockIdx.x * BN;

    int which = blockIdx.x;
    bool doPT = (which < 2);
    float* ptdst = out + 2 * NUM_E + (size_t)which * NUM_E * MEMD;

    int rowA = wm * 16 + (lane & 15);
    int kA   = (lane >> 4) * 8;
    int rowB = wn * 32 + (lane & 7) + ((lane >> 4) & 1) * 8;
    int kB   = ((lane >> 3) & 1) * 8;

    const __half* wsrc[2] = { g_wl, g_wd };

    float acc[3][4][4];
    #pragma unroll
    for (int a = 0; a < 3; a++)
        #pragma unroll
        for (int b = 0; b < 4; b++)
            #pragma unroll
            for (int c = 0; c < 4; c++) acc[a][b][c] = 0.f;

    // --- stage ids / rel-times for this m-block ---
    if (tid < 192) {
        int g = tid / 64, r = tid % 64;
        sm_id[tid] = g_id3[g * E_PAD + m0 + r];
        sm_rt[tid] = g_rt3[g * E_PAD + m0 + r];
    }

    // W tile loader (cp.async, as R7)
    auto loadW = [&](int ch, int stg) {
        int k0 = ch * KB;
        uint32_t sb = sbase + (uint32_t)(stg * STAGE_H + ZHALVES) * 2;
        #pragma unroll
        for (int p = 0; p < 4; p++) {
            int id  = tid + p * 256;
            int mat = id >> 9;
            int rem = id & 511;
            int row = rem >> 3;
            int c8  = (rem & 7) << 3;
            const __half* src = wsrc[mat] + (size_t)(n0 + row) * DZ + k0 + c8;
            uint32_t dst = sb + (uint32_t)(((mat * 64 + row) * WSTR + c8) * 2);
            asm volatile("cp.async.cg.shared.global [%0], [%1], 16;" :: "r"(dst), "l"(src));
        }
        asm volatile("cp.async.commit_group;");
    };

    int f4c = (tid & 15) * 4;     // column offset within chunk (floats)
    int rbase = tid >> 4;         // row sub-index

    // gathered-Z loaders: group g == matrix (0=zs src,1=zp,2=zn)
    auto z_ldg = [&](int chn, int g, float4* v) {
        #pragma unroll
        for (int p = 0; p < 4; p++) {
            int r = p * 16 + rbase;
            int gid = sm_id[g * 64 + r];
            const float* srcp = (chn < 4)
                ? mem + (size_t)gid * MEMD  + chn * 64 + f4c
                : x   + (size_t)gid * NODED + (chn - 4) * 64 + f4c;
            v[p] = *(const float4*)srcp;
        }
    };
    auto z_sts = [&](int chn, int g, float4* v, int dstg) {
        int c = chn * 64 + f4c;   // z-space column
        const float* wsel = (g == 0) ? wps : wpd;
        const float* bsel = (g == 0) ? bps : bpd;
        float4 w4 = *(const float4*)(wsel + c);
        float4 b4 = *(const float4*)(bsel + c);
        __half* zd = sm + dstg * STAGE_H;
        #pragma unroll
        for (int p = 0; p < 4; p++) {
            int r = p * 16 + rbase;
            float rt = sm_rt[g * 64 + r];
            float sx = (1.f + rt * w4.x + b4.x) * v[p].x;
            float sy = (1.f + rt * w4.y + b4.y) * v[p].y;
            float sz = (1.f + rt * w4.z + b4.z) * v[p].z;
            float sw = (1.f + rt * w4.w + b4.w) * v[p].w;
            __half2 h0 = __floats2half2_rn(sx, sy);
            __half2 h1 = __floats2half2_rn(sz, sw);
            *(uint2*)(zd + (g * 64 + r) * ZSTR + f4c) =
                make_uint2(*(uint32_t*)&h0, *(uint32_t*)&h1);
        }
    };

    __syncthreads();   // ids/rts visible

    // prologue: gather chunk 0 into stage 0 (synchronous), start W(0)
    {
        float4 v[4];
        #pragma unroll
        for (int g = 0; g < 3; g++) { z_ldg(0, g, v); z_sts(0, g, v, 0); }
    }
    loadW(0, 0);

    int stg = 0;
    for (int ch = 0; ch < NCH; ch++) {
        asm volatile("cp.async.wait_group 0;");
        __syncthreads();   // W(ch) + Z(ch) visible; prior-stage reads done

        if (ch + 1 < NCH) loadW(ch + 1, stg ^ 1);

        // passthrough copy (reads L2-hot; 3 float4 per chunk)
        if (doPT) {
            #pragma unroll
            for (int q = 0; q < 3; q++) {
                int p = ch * 3 + q;
                if (p < 16) {
                    int f = p * 256 + tid;
                    int er = f >> 6;
                    int e  = m0 + er;
                    int c4 = (f & 63) * 4;
                    if (e < NUM_E) {
                        int gid = sm_id[which * 64 + er];
                        float4 pv = *(const float4*)(mem + (size_t)gid * MEMD + c4);
                        *(float4*)(ptdst + (size_t)e * MEMD + c4) = pv;
                    }
                }
            }
        }

        uint32_t zb = sbase + (uint32_t)(stg * STAGE_H) * 2;
        uint32_t wb = zb + (uint32_t)ZHALVES * 2;
        bool more = (ch + 1 < NCH);
        float4 v[4];

        auto mma_step = [&](int kk) {
            uint32_t afr[3][4];
            uint32_t bfr[2][2][4];
            #pragma unroll
            for (int mat = 0; mat < 3; mat++) {
                uint32_t a = zb + (uint32_t)(((mat * 64 + rowA) * ZSTR + kk + kA) * 2);
                ldsm4(afr[mat], a);
            }
            #pragma unroll
            for (int mat = 0; mat < 2; mat++)
                #pragma unroll
                for (int pr = 0; pr < 2; pr++) {
                    uint32_t a = wb + (uint32_t)(((mat * 64 + rowB + pr * 16) * WSTR + kk + kB) * 2);
                    ldsm4(bfr[mat][pr], a);
                }
            #pragma unroll
            for (int pr = 0; pr < 2; pr++)
                #pragma unroll
                for (int h = 0; h < 2; h++) {
                    int nt = pr * 2 + h;
                    mma_f16(acc[0][nt], afr[0][0], afr[0][1], afr[0][2], afr[0][3],
                            bfr[0][pr][2 * h], bfr[0][pr][2 * h + 1]);
                    mma_f16(acc[1][nt], afr[1][0], afr[1][1], afr[1][2], afr[1][3],
                            bfr[1][pr][2 * h], bfr[1][pr][2 * h + 1]);
                    mma_f16(acc[2][nt], afr[2][0], afr[2][1], afr[2][2], afr[2][3],
                            bfr[1][pr][2 * h], bfr[1][pr][2 * h + 1]);
                }
        };

        if (more) z_ldg(ch + 1, 0, v);
        mma_step(0);
        if (more) { z_sts(ch + 1, 0, v, stg ^ 1); z_ldg(ch + 1, 1, v); }
        mma_step(16);
        if (more) { z_sts(ch + 1, 1, v, stg ^ 1); z_ldg(ch + 1, 2, v); }
        mma_step(32);
        if (more) { z_sts(ch + 1, 2, v, stg ^ 1); }
        mma_step(48);

        stg ^= 1;
    }

    // --- epilogue: bias + relu + final-dot partials over this block's N ---
    float pp0 = 0.f, pp1 = 0.f, pn0 = 0.f, pn1 = 0.f;
    #pragma unroll
    for (int nt = 0; nt < 4; nt++) {
        #pragma unroll
        for (int j = 0; j < 2; j++) {
            int n = n0 + wn * 32 + nt * 8 + 2 * qid + j;
            float bias = bl[n] + bd[n];
            float wfn  = wf[n];
            float c0 = acc[0][nt][j]     + acc[1][nt][j]     + bias;
            float c1 = acc[0][nt][2 + j] + acc[1][nt][2 + j] + bias;
            pp0 += fmaxf(c0, 0.f) * wfn;
            pp1 += fmaxf(c1, 0.f) * wfn;
            float d0 = acc[0][nt][j]     + acc[2][nt][j]     + bias;
            float d1 = acc[0][nt][2 + j] + acc[2][nt][2 + j] + bias;
            pn0 += fmaxf(d0, 0.f) * wfn;
            pn1 += fmaxf(d1, 0.f) * wfn;
        }
    }
    #pragma unroll
    for (int s = 1; s < 4; s <<= 1) {
        pp0 += __shfl_xor_sync(0xffffffffu, pp0, s);
        pp1 += __shfl_xor_sync(0xffffffffu, pp1, s);
        pn0 += __shfl_xor_sync(0xffffffffu, pn0, s);
        pn1 += __shfl_xor_sync(0xffffffffu, pn1, s);
    }
    if (qid == 0) {
        int e0 = m0 + wm * 16 + grp;
        int e1 = e0 + 8;
        if (e0 < NUM_E) {
            atomicAdd(&out[e0],         pp0);
            atomicAdd(&out[NUM_E + e0], pn0);
        }
        if (e1 < NUM_E) {
            atomicAdd(&out[e1],         pp1);
            atomicAdd(&out[NUM_E + e1], pn1);
        }
    }
}

// ---------------------------------------------------------------------------
extern "C" void kernel_launch(void* const* d_in, const int* in_sizes, int n_in,
                              void* d_out, int out_size) {
    const float* mem  = (const float*)d_in[0];
    const float* lu   = (const float*)d_in[1];
    const float* x    = (const float*)d_in[2];
    const float* bt   = (const float*)d_in[3];
    const float* wps  = (const float*)d_in[4];
    const float* bps  = (const float*)d_in[5];
    const float* wpd  = (const float*)d_in[6];
    const float* bpd  = (const float*)d_in[7];
    const float* wl   = (const float*)d_in[8];
    const float* bl   = (const float*)d_in[9];
    const float* wd   = (const float*)d_in[10];
    const float* bd   = (const float*)d_in[11];
    const float* wf   = (const float*)d_in[12];
    const float* bf   = (const float*)d_in[13];
    const int*   nid  = (const int*)d_in[14];
    const int*   idm  = (const int*)d_in[15];
    const int*   src  = (const int*)d_in[16];
    const int*   pds  = (const int*)d_in[17];
    const int*   nds  = (const int*)d_in[18];
    float* out = (float*)d_out;

    cudaFuncSetAttribute(gemm_fused,
                         cudaFuncAttributeMaxDynamicSharedMemorySize, SMEM_BYTES);

    dim3 rgrid((E_PAD + 255) / 256, 4);   // y=0..2 resolve (padded), y=3 convw
    resolve<<<rgrid, 256>>>(lu, bt, bf, wl, wd, nid, idm, src, pds, nds, out);

    dim3 grid(DZ / BN, E_PAD / BM);   // (6, 1564)
    gemm_fused<<<grid, 256, SMEM_BYTES>>>(mem, x, wps, bps, wpd, bpd,
                                          bl, bd, wf, out);
}

// round 16
// speedup vs baseline: 1.3457x; 1.3457x over previous
#include <cuda_runtime.h>
#include <cuda_fp16.h>
#include <cstdint>

#define NUM_E 100000
#define DZ    384
#define MEMD  256
#define NODED 128
#define E_PAD 100096           // 1564 * 64
#define BM 64
#define BN 64
#define KB 64                  // K halves per chunk
#define NCH (DZ/KB)            // 6 chunks

#define ZSTR 72                // padded row stride in halves -> conflict-free
#define WSTR 72
#define ZHALVES (3*64*ZSTR)    // 13824 halves per stage (Z part)
#define WHALVES (2*64*WSTR)    // 9216 halves per stage (W part)
#define STAGE_H (ZHALVES + WHALVES)       // 23040 halves
#define SMEM_BYTES (2 * STAGE_H * 2)      // 92160 B

// fp16 scratch (zero-initialized .bss; rows >= NUM_E stay zero = safe padding)
__device__ __align__(16) __half g_zs[(size_t)E_PAD * DZ];
__device__ __align__(16) __half g_zp[(size_t)E_PAD * DZ];
__device__ __align__(16) __half g_zn[(size_t)E_PAD * DZ];
__device__ __align__(16) __half g_wl[DZ * DZ];
__device__ __align__(16) __half g_wd[DZ * DZ];
// per-edge resolved ids / rel-times: [which*NUM_E + e]
__device__ int   g_id3[3 * NUM_E];
__device__ float g_rt3[3 * NUM_E];

__device__ __forceinline__ void mma_f16(float* c,
    uint32_t a0, uint32_t a1, uint32_t a2, uint32_t a3,
    uint32_t b0, uint32_t b1)
{
    asm volatile(
        "mma.sync.aligned.m16n8k16.row.col.f32.f16.f16.f32 "
        "{%0,%1,%2,%3},{%4,%5,%6,%7},{%8,%9},{%0,%1,%2,%3};"
        : "+f"(c[0]), "+f"(c[1]), "+f"(c[2]), "+f"(c[3])
        : "r"(a0), "r"(a1), "r"(a2), "r"(a3), "r"(b0), "r"(b1));
}
__device__ __forceinline__ void ldsm4(uint32_t* r, uint32_t addr) {
    asm volatile("ldmatrix.sync.aligned.m8n8.x4.shared.b16 {%0,%1,%2,%3}, [%4];"
                 : "=r"(r[0]), "=r"(r[1]), "=r"(r[2]), "=r"(r[3]) : "r"(addr));
}

// ---------------------------------------------------------------------------
// Resolve (+ fused weight conversion): y in {0,1,2} resolves id chains fully
// in parallel; y == 3 converts weights. Seeds scalar outputs with b_final.
// ---------------------------------------------------------------------------
__global__ void resolve(
    const float* __restrict__ lu, const float* __restrict__ bt,
    const float* __restrict__ bfin,
    const float* __restrict__ wlf, const float* __restrict__ wdf,
    const int* __restrict__ nid, const int* __restrict__ idmap,
    const int* __restrict__ src, const int* __restrict__ pdst,
    const int* __restrict__ ndst,
    float* __restrict__ out)
{
    int e = blockIdx.x * blockDim.x + threadIdx.x;
    int w = blockIdx.y;
    if (w == 3) {
        for (int i = e; i < DZ * DZ; i += gridDim.x * blockDim.x) {
            g_wl[i] = __float2half_rn(wlf[i]);
            g_wd[i] = __float2half_rn(wdf[i]);
        }
        return;
    }
    if (e >= NUM_E) return;
    const int* idx = (w == 0) ? src : (w == 1) ? pdst : ndst;
    int g = nid[idmap[idx[e]]];
    g_id3[w * NUM_E + e] = g;
    g_rt3[w * NUM_E + e] = fabsf(lu[g] - bt[e]);
    if (w == 0) {
        float bfv = bfin[0];
        out[e]         = bfv;   // seed with b_final; GEMM atomically adds
        out[NUM_E + e] = bfv;
    }
}

// ---------------------------------------------------------------------------
// Gather (R7 champion): 96 threads per edge, float4 loads, half2 stores,
// passthrough outputs written from the already-loaded registers.
// ---------------------------------------------------------------------------
__global__ __launch_bounds__(96) void gather96(
    const float* __restrict__ mem, const float* __restrict__ x,
    const float* __restrict__ wps, const float* __restrict__ bps,
    const float* __restrict__ wpd, const float* __restrict__ bpd,
    float* __restrict__ out)
{
    int e = blockIdx.x;
    int t = threadIdx.x;
    int c = t * 4;
    bool isMem = (c < MEMD);

    int gs = g_id3[e], gp = g_id3[NUM_E + e], gn = g_id3[2 * NUM_E + e];
    float rts = g_rt3[e], rtp = g_rt3[NUM_E + e], rtn = g_rt3[2 * NUM_E + e];

    float4 ws4 = *(const float4*)(wps + c);
    float4 bs4 = *(const float4*)(bps + c);
    float4 wd4 = *(const float4*)(wpd + c);
    float4 bd4 = *(const float4*)(bpd + c);

    float4 ss, sp, sn;
    ss.x = 1.f + rts * ws4.x + bs4.x; ss.y = 1.f + rts * ws4.y + bs4.y;
    ss.z = 1.f + rts * ws4.z + bs4.z; ss.w = 1.f + rts * ws4.w + bs4.w;
    sp.x = 1.f + rtp * wd4.x + bd4.x; sp.y = 1.f + rtp * wd4.y + bd4.y;
    sp.z = 1.f + rtp * wd4.z + bd4.z; sp.w = 1.f + rtp * wd4.w + bd4.w;
    sn.x = 1.f + rtn * wd4.x + bd4.x; sn.y = 1.f + rtn * wd4.y + bd4.y;
    sn.z = 1.f + rtn * wd4.z + bd4.z; sn.w = 1.f + rtn * wd4.w + bd4.w;

    float4 vs, vp, vn;
    if (isMem) {
        vs = *(const float4*)(mem + (size_t)gs * MEMD + c);
        vp = *(const float4*)(mem + (size_t)gp * MEMD + c);
        vn = *(const float4*)(mem + (size_t)gn * MEMD + c);
        float* msrc = out + 2 * NUM_E + (size_t)e * MEMD;
        float* mpos = out + 2 * NUM_E + (size_t)NUM_E * MEMD + (size_t)e * MEMD;
        *(float4*)(msrc + c) = vs;
        *(float4*)(mpos + c) = vp;
    } else {
        int cx = c - MEMD;
        vs = *(const float4*)(x + (size_t)gs * NODED + cx);
        vp = *(const float4*)(x + (size_t)gp * NODED + cx);
        vn = *(const float4*)(x + (size_t)gn * NODED + cx);
    }

    size_t off = (size_t)e * DZ + c;
    {
        __half2 h0 = __floats2half2_rn(vs.x * ss.x, vs.y * ss.y);
        __half2 h1 = __floats2half2_rn(vs.z * ss.z, vs.w * ss.w);
        *(uint2*)(g_zs + off) = make_uint2(*(uint32_t*)&h0, *(uint32_t*)&h1);
    }
    {
        __half2 h0 = __floats2half2_rn(vp.x * sp.x, vp.y * sp.y);
        __half2 h1 = __floats2half2_rn(vp.z * sp.z, vp.w * sp.w);
        *(uint2*)(g_zp + off) = make_uint2(*(uint32_t*)&h0, *(uint32_t*)&h1);
    }
    {
        __half2 h0 = __floats2half2_rn(vn.x * sn.x, vn.y * sn.y);
        __half2 h1 = __floats2half2_rn(vn.z * sn.z, vn.w * sn.w);
        *(uint2*)(g_zn + off) = make_uint2(*(uint32_t*)&h0, *(uint32_t*)&h1);
    }
}

// ---------------------------------------------------------------------------
// Kernel B: R7 champion GEMM, but ONE barrier per chunk. The single top
// barrier both publishes chunk ch (after wait_group) and guarantees all
// warps finished reading stage stg^1 in compute(ch-1) before load_chunk
// (ch+1) overwrites it. cp.async(ch+1) still overlaps compute(ch).
// ---------------------------------------------------------------------------
__global__ __launch_bounds__(256, 2) void gemm_readout(
    const float* __restrict__ bl, const float* __restrict__ bd,
    const float* __restrict__ wf,
    float* __restrict__ out)
{
    extern __shared__ __half sm[];
    uint32_t sbase = (uint32_t)__cvta_generic_to_shared(sm);

    int tid  = threadIdx.x;
    int wid  = tid >> 5, lane = tid & 31;
    int grp  = lane >> 2, qid = lane & 3;
    int wm   = wid & 3,  wn  = wid >> 2;     // 4 M-warps x 2 N-warps
    int m0   = blockIdx.y * BM;
    int n0   = blockIdx.x * BN;

    int rowA = wm * 16 + (lane & 15);
    int kA   = (lane >> 4) * 8;
    int rowB = wn * 32 + (lane & 7) + ((lane >> 4) & 1) * 8;  // + pr*16
    int kB   = ((lane >> 3) & 1) * 8;

    const __half* zsrc[3] = { g_zs, g_zp, g_zn };
    const __half* wsrc[2] = { g_wl, g_wd };

    float acc[3][4][4];
    #pragma unroll
    for (int a = 0; a < 3; a++)
        #pragma unroll
        for (int b = 0; b < 4; b++)
            #pragma unroll
            for (int c = 0; c < 4; c++) acc[a][b][c] = 0.f;

    auto load_chunk = [&](int ch, int stg) {
        int k0 = ch * KB;
        uint32_t sb = sbase + (uint32_t)(stg * STAGE_H) * 2;
        #pragma unroll
        for (int p = 0; p < 6; p++) {           // Z: 3 mats * 64 rows * 8 x 16B
            int id  = tid + p * 256;
            int mat = id >> 9;
            int rem = id & 511;
            int row = rem >> 3;
            int c8  = (rem & 7) << 3;
            const __half* src = zsrc[mat] + (size_t)(m0 + row) * DZ + k0 + c8;
            uint32_t dst = sb + (uint32_t)(((mat * 64 + row) * ZSTR + c8) * 2);
            asm volatile("cp.async.cg.shared.global [%0], [%1], 16;" :: "r"(dst), "l"(src));
        }
        #pragma unroll
        for (int p = 0; p < 4; p++) {           // W: 2 mats * 64 rows * 8 x 16B
            int id  = tid + p * 256;
            int mat = id >> 9;
            int rem = id & 511;
            int row = rem >> 3;
            int c8  = (rem & 7) << 3;
            const __half* src = wsrc[mat] + (size_t)(n0 + row) * DZ + k0 + c8;
            uint32_t dst = sb + (uint32_t)((ZHALVES + (mat * 64 + row) * WSTR + c8) * 2);
            asm volatile("cp.async.cg.shared.global [%0], [%1], 16;" :: "r"(dst), "l"(src));
        }
        asm volatile("cp.async.commit_group;");
    };

    load_chunk(0, 0);
    int stg = 0;
    for (int ch = 0; ch < NCH; ch++) {
        asm volatile("cp.async.wait_group 0;");   // chunk ch resident
        __syncthreads();                          // publish + WAR fence

        if (ch + 1 < NCH) load_chunk(ch + 1, stg ^ 1);   // overlaps compute

        uint32_t zb = sbase + (uint32_t)(stg * STAGE_H) * 2;
        uint32_t wb = zb + (uint32_t)ZHALVES * 2;

        #pragma unroll
        for (int kk = 0; kk < KB; kk += 16) {
            uint32_t afr[3][4];
            uint32_t bfr[2][2][4];
            #pragma unroll
            for (int mat = 0; mat < 3; mat++) {
                uint32_t a = zb + (uint32_t)(((mat * 64 + rowA) * ZSTR + kk + kA) * 2);
                ldsm4(afr[mat], a);
            }
            #pragma unroll
            for (int mat = 0; mat < 2; mat++)
                #pragma unroll
                for (int pr = 0; pr < 2; pr++) {
                    uint32_t a = wb + (uint32_t)(((mat * 64 + rowB + pr * 16) * WSTR + kk + kB) * 2);
                    ldsm4(bfr[mat][pr], a);
                }
            #pragma unroll
            for (int pr = 0; pr < 2; pr++)
                #pragma unroll
                for (int h = 0; h < 2; h++) {
                    int nt = pr * 2 + h;
                    mma_f16(acc[0][nt], afr[0][0], afr[0][1], afr[0][2], afr[0][3],
                            bfr[0][pr][2 * h], bfr[0][pr][2 * h + 1]);
                    mma_f16(acc[1][nt], afr[1][0], afr[1][1], afr[1][2], afr[1][3],
                            bfr[1][pr][2 * h], bfr[1][pr][2 * h + 1]);
                    mma_f16(acc[2][nt], afr[2][0], afr[2][1], afr[2][2], afr[2][3],
                            bfr[1][pr][2 * h], bfr[1][pr][2 * h + 1]);
                }
        }
        stg ^= 1;
    }

    // --- epilogue: bias + relu + final-dot partials over this block's N ---
    float pp0 = 0.f, pp1 = 0.f, pn0 = 0.f, pn1 = 0.f;
    #pragma unroll
    for (int nt = 0; nt < 4; nt++) {
        #pragma unroll
        for (int j = 0; j < 2; j++) {
            int n = n0 + wn * 32 + nt * 8 + 2 * qid + j;
            float bias = bl[n] + bd[n];
            float wfn  = wf[n];
            float c0 = acc[0][nt][j]     + acc[1][nt][j]     + bias;
            float c1 = acc[0][nt][2 + j] + acc[1][nt][2 + j] + bias;
            pp0 += fmaxf(c0, 0.f) * wfn;
            pp1 += fmaxf(c1, 0.f) * wfn;
            float d0 = acc[0][nt][j]     + acc[2][nt][j]     + bias;
            float d1 = acc[0][nt][2 + j] + acc[2][nt][2 + j] + bias;
            pn0 += fmaxf(d0, 0.f) * wfn;
            pn1 += fmaxf(d1, 0.f) * wfn;
        }
    }
    #pragma unroll
    for (int s = 1; s < 4; s <<= 1) {
        pp0 += __shfl_xor_sync(0xffffffffu, pp0, s);
        pp1 += __shfl_xor_sync(0xffffffffu, pp1, s);
        pn0 += __shfl_xor_sync(0xffffffffu, pn0, s);
        pn1 += __shfl_xor_sync(0xffffffffu, pn1, s);
    }
    if (qid == 0) {
        int e0 = m0 + wm * 16 + grp;
        int e1 = e0 + 8;
        if (e0 < NUM_E) {
            atomicAdd(&out[e0],         pp0);
            atomicAdd(&out[NUM_E + e0], pn0);
        }
        if (e1 < NUM_E) {
            atomicAdd(&out[e1],         pp1);
            atomicAdd(&out[NUM_E + e1], pn1);
        }
    }
}

// ---------------------------------------------------------------------------
extern "C" void kernel_launch(void* const* d_in, const int* in_sizes, int n_in,
                              void* d_out, int out_size) {
    const float* mem  = (const float*)d_in[0];
    const float* lu   = (const float*)d_in[1];
    const float* x    = (const float*)d_in[2];
    const float* bt   = (const float*)d_in[3];
    const float* wps  = (const float*)d_in[4];
    const float* bps  = (const float*)d_in[5];
    const float* wpd  = (const float*)d_in[6];
    const float* bpd  = (const float*)d_in[7];
    const float* wl   = (const float*)d_in[8];
    const float* bl   = (const float*)d_in[9];
    const float* wd   = (const float*)d_in[10];
    const float* bd   = (const float*)d_in[11];
    const float* wf   = (const float*)d_in[12];
    const float* bf   = (const float*)d_in[13];
    const int*   nid  = (const int*)d_in[14];
    const int*   idm  = (const int*)d_in[15];
    const int*   src  = (const int*)d_in[16];
    const int*   pds  = (const int*)d_in[17];
    const int*   nds  = (const int*)d_in[18];
    float* out = (float*)d_out;

    cudaFuncSetAttribute(gemm_readout,
                         cudaFuncAttributeMaxDynamicSharedMemorySize, SMEM_BYTES);

    dim3 rgrid((NUM_E + 255) / 256, 4);   // y=0..2 resolve, y=3 convw
    resolve<<<rgrid, 256>>>(lu, bt, bf, wl, wd, nid, idm, src, pds, nds, out);

    gather96<<<NUM_E, 96>>>(mem, x, wps, bps, wpd, bpd, out);

    dim3 grid(DZ / BN, E_PAD / BM);   // (6, 1564)
    gemm_readout<<<grid, 256, SMEM_BYTES>>>(bl, bd, wf, out);
}